// round 1
// baseline (speedup 1.0000x reference)
#include <cuda_runtime.h>

#define VDIM   50257
#define BDIM   2048
#define KSEL   500
#define NTH    512
#define NW     16          // warps per CTA
#define NGRP   4           // histogram privatization groups (round 1)
#define LISTCAP 4096
#define MARGIN_C 0.2f
#define IGNORE_IDX 0

__device__ float g_rowloss[BDIM];

static __device__ __forceinline__ unsigned fkey(float f){
    unsigned u = __float_as_uint(f);
    return (u & 0x80000000u) ? ~u : (u | 0x80000000u);
}
static __device__ __forceinline__ float kinv(unsigned u){
    unsigned b = (u & 0x80000000u) ? (u & 0x7FFFFFFFu) : ~u;
    return __uint_as_float(b);
}

// Find bucket b s.t. S(b+1) < kk <= S(b) where S(b)=sum_{x>=b} hist[x].
// Updates kk -> kk - S(b+1). All threads must call.
static __device__ __forceinline__ void select_bucket(
    const unsigned* hists, int ngrp, unsigned& kk, unsigned& bucket,
    unsigned* wtot, unsigned* selb, unsigned* selk)
{
    const int tid = threadIdx.x;
    const int lane = tid & 31;
    unsigned cnt = 0, s = 0;
    if (tid < 256){
        for (int g = 0; g < ngrp; ++g) cnt += hists[g*256 + tid];
        s = cnt;
        #pragma unroll
        for (int o = 1; o < 32; o <<= 1){
            unsigned t = __shfl_down_sync(0xffffffffu, s, o);
            if (lane + o < 32) s += t;
        }
        if (lane == 0) wtot[tid >> 5] = s;   // warp total (sum of its 32 buckets)
    }
    __syncthreads();
    if (tid < 256){
        unsigned Sb = s;
        for (int w = (tid >> 5) + 1; w < 8; ++w) Sb += wtot[w];
        unsigned Snext = Sb - cnt;
        if (Sb >= kk && Snext < kk){ *selb = (unsigned)tid; *selk = kk - Snext; }
    }
    __syncthreads();
    bucket = *selb;
    kk = *selk;
    __syncthreads();
}

__global__ void __launch_bounds__(NTH, 1)
adalab_kernel(const float* __restrict__ output,
              const int*   __restrict__ target,
              const float* __restrict__ scores)
{
    extern __shared__ unsigned dynsm[];
    unsigned* skeys = dynsm;                              // VDIM keys
    unsigned* hists = dynsm + VDIM;                       // NGRP*256
    int*      list  = (int*)(dynsm + VDIM + NGRP*256);    // LISTCAP

    __shared__ float    s_redf[NW];
    __shared__ float    s_rA[NW], s_rB[NW], s_rC[NW];
    __shared__ unsigned s_t2a[NW], s_t2b[NW];
    __shared__ unsigned s_wtot[8];
    __shared__ unsigned s_selb, s_selk;
    __shared__ int      s_nlist;
    __shared__ float    s_ot;

    const int tid  = threadIdx.x;
    const int lane = tid & 31;
    const int wid  = tid >> 5;
    const int row  = blockIdx.x;
    const int tgt  = target[row];
    const float* orow = output + (size_t)row * VDIM;
    const float* srow = scores + (size_t)row * VDIM;
    const float NEGINF = __int_as_float(0xff800000);

    // ---------- pass 1: max(output) and output[target] ----------
    float omax = NEGINF;
    {
        int j = tid;
        for (; j + 3*NTH < VDIM; j += 4*NTH){
            float a = orow[j], b = orow[j+NTH], c = orow[j+2*NTH], d = orow[j+3*NTH];
            omax = fmaxf(fmaxf(fmaxf(omax, a), b), fmaxf(c, d));
        }
        for (; j < VDIM; j += NTH) omax = fmaxf(omax, orow[j]);
    }
    #pragma unroll
    for (int o = 16; o; o >>= 1) omax = fmaxf(omax, __shfl_xor_sync(0xffffffffu, omax, o));
    if (!lane) s_redf[wid] = omax;
    if (tid == 0) s_ot = orow[tgt];
    __syncthreads();
    if (wid == 0){
        float x = (lane < NW) ? s_redf[lane] : NEGINF;
        #pragma unroll
        for (int o = 8; o; o >>= 1) x = fmaxf(x, __shfl_xor_sync(0xffffffffu, x, o));
        if (!lane) s_redf[0] = x;
    }
    __syncthreads();
    const float o_max = s_redf[0];
    const float o_t   = s_ot;

    // ---------- pass 2: load keys into SMEM, track top-2 ----------
    unsigned t2a = 0, t2b = 0;
    {
        int j = tid;
        for (; j < VDIM; j += NTH){
            float f = srow[j];
            unsigned u = (j == tgt || j == IGNORE_IDX) ? 0u : fkey(f);
            skeys[j] = u;
            if (u > t2a){ t2b = t2a; t2a = u; }
            else if (u > t2b) t2b = u;
        }
    }
    #pragma unroll
    for (int o = 16; o; o >>= 1){
        unsigned ya = __shfl_xor_sync(0xffffffffu, t2a, o);
        unsigned yb = __shfl_xor_sync(0xffffffffu, t2b, o);
        if (ya > t2a){ t2b = max(t2a, yb); t2a = ya; }
        else         { t2b = max(t2b, ya); }
    }
    if (!lane){ s_t2a[wid] = t2a; s_t2b[wid] = t2b; }
    __syncthreads();
    if (wid == 0){
        unsigned xa = (lane < NW) ? s_t2a[lane] : 0u;
        unsigned xb = (lane < NW) ? s_t2b[lane] : 0u;
        #pragma unroll
        for (int o = 8; o; o >>= 1){
            unsigned ya = __shfl_xor_sync(0xffffffffu, xa, o);
            unsigned yb = __shfl_xor_sync(0xffffffffu, xb, o);
            if (ya > xa){ xb = max(xa, yb); xa = ya; }
            else        { xb = max(xb, ya); }
        }
        if (!lane){ s_t2a[0] = xa; s_t2b[0] = xb; }
    }
    __syncthreads();
    const unsigned k2key = s_t2b[0];
    const float s2 = kinv(k2key);

    // ---------- radix select: exact 500th-largest key ----------
    unsigned prefix = 0;
    unsigned kk = KSEL;
    const int niter = (VDIM + NTH - 1) / NTH;

    // Round 1: top byte, privatized histograms
    for (int i = tid; i < NGRP*256; i += NTH) hists[i] = 0;
    if (tid == 0) s_nlist = 0;
    __syncthreads();
    for (int it = 0; it < niter; ++it){
        int j = it*NTH + tid;
        bool in = j < VDIM;
        unsigned u = in ? skeys[j] : 0u;
        unsigned d = u >> 24;
        unsigned tag = in ? d : (0x100u + (unsigned)lane);
        unsigned mm = __match_any_sync(0xffffffffu, tag);
        if (in && lane == (__ffs(mm) - 1))
            atomicAdd(&hists[(tid >> 7)*256 + d], (unsigned)__popc(mm));
    }
    __syncthreads();
    unsigned b1;
    select_bucket(hists, NGRP, kk, b1, s_wtot, &s_selb, &s_selk);
    prefix = b1 << 24;

    // Round 2: second byte among bucket==b1; compact candidate indices (top byte >= b1)
    for (int i = tid; i < 256; i += NTH) hists[i] = 0;
    __syncthreads();
    for (int it = 0; it < niter; ++it){
        int j = it*NTH + tid;
        bool in = j < VDIM;
        unsigned u = in ? skeys[j] : 0u;
        unsigned top = u >> 24;
        bool ge = in && (top >= b1);
        unsigned bal = __ballot_sync(0xffffffffu, ge);
        if (bal){
            int ldr = __ffs(bal) - 1;
            int base = 0;
            if (lane == ldr) base = atomicAdd(&s_nlist, __popc(bal));
            base = __shfl_sync(0xffffffffu, base, ldr);
            if (ge){
                int pos = base + __popc(bal & ((1u << lane) - 1u));
                if (pos < LISTCAP) list[pos] = j;
            }
        }
        bool ok = in && (top == b1);
        unsigned d = (u >> 16) & 255u;
        unsigned tag = ok ? d : (0x100u + (unsigned)lane);
        unsigned mm = __match_any_sync(0xffffffffu, tag);
        if (ok && lane == (__ffs(mm) - 1))
            atomicAdd(&hists[d], (unsigned)__popc(mm));
    }
    __syncthreads();
    unsigned b2;
    select_bucket(hists, 1, kk, b2, s_wtot, &s_selb, &s_selk);
    prefix |= b2 << 16;

    const int nl = s_nlist;
    const bool useList = (nl <= LISTCAP);
    const int ncand = useList ? nl : VDIM;

    // Rounds 3 & 4: scan candidate list only (tiny)
    for (int shift = 8; shift >= 0; shift -= 8){
        for (int i = tid; i < 256; i += NTH) hists[i] = 0;
        __syncthreads();
        const unsigned pref_hi = (unsigned)(((unsigned long long)prefix) >> (shift + 8));
        const int nit = (ncand + NTH - 1) / NTH;
        for (int it = 0; it < nit; ++it){
            int i = it*NTH + tid;
            bool in = i < ncand;
            int j = in ? (useList ? list[i] : i) : 0;
            unsigned u = in ? skeys[j] : 0u;
            bool ok = in && ((unsigned)(((unsigned long long)u) >> (shift + 8)) == pref_hi);
            unsigned d = (u >> shift) & 255u;
            unsigned tag = ok ? d : (0x100u + (unsigned)lane);
            unsigned mm = __match_any_sync(0xffffffffu, tag);
            if (ok && lane == (__ffs(mm) - 1))
                atomicAdd(&hists[d], (unsigned)__popc(mm));
        }
        __syncthreads();
        unsigned b;
        select_bucket(hists, 1, kk, b, s_wtot, &s_selb, &s_selk);
        prefix |= b << shift;
    }
    const unsigned kthkey = prefix;

    // ---------- final: Z, S1, S2 over kept entries [kth, k2] ----------
    float Z = 0.f, S1 = 0.f, S2 = 0.f;
    {
        const int nit = (ncand + NTH - 1) / NTH;
        for (int it = 0; it < nit; ++it){
            int i = it*NTH + tid;
            if (i < ncand){
                int j = useList ? list[i] : i;
                unsigned u = skeys[j];
                if (u >= kthkey && u <= k2key){
                    float sv = kinv(u);
                    float e = expf(sv - s2);
                    Z  += e;
                    S1 += e * sv;
                    S2 += e * __ldg(orow + j);
                }
            }
        }
    }
    #pragma unroll
    for (int o = 16; o; o >>= 1){
        Z  += __shfl_xor_sync(0xffffffffu, Z,  o);
        S1 += __shfl_xor_sync(0xffffffffu, S1, o);
        S2 += __shfl_xor_sync(0xffffffffu, S2, o);
    }
    if (!lane){ s_rA[wid] = Z; s_rB[wid] = S1; s_rC[wid] = S2; }
    __syncthreads();
    if (wid == 0){
        float a = (lane < NW) ? s_rA[lane] : 0.f;
        float b = (lane < NW) ? s_rB[lane] : 0.f;
        float c = (lane < NW) ? s_rC[lane] : 0.f;
        #pragma unroll
        for (int o = 8; o; o >>= 1){
            a += __shfl_xor_sync(0xffffffffu, a, o);
            b += __shfl_xor_sync(0xffffffffu, b, o);
            c += __shfl_xor_sync(0xffffffffu, c, o);
        }
        if (!lane){
            float loss = 0.f;
            if (tgt != IGNORE_IDX){
                float Zt = a, S1t = b, S2t = c;
                float vmax = 1.0f / Zt;
                float pm = expf(o_max);
                float pg = expf(o_t);
                float eps0 = 1.0f - pm;
                float ub   = 1.0f / (1.0f + vmax) - MARGIN_C;
                float eps1 = (eps0 > ub) ? ub : eps0;
                float al = pg / pm; al *= al;
                float eps = al * eps1;
                float conf = 1.0f - eps;
                if (eps  > 0.f) loss += eps  * (logf(eps)  - s2 - logf(Zt) + (S1t - S2t) / Zt);
                if (conf > 0.f) loss += conf * (logf(conf) - o_t);
            }
            g_rowloss[row] = loss;
        }
    }
}

__global__ void finalize_kernel(float* __restrict__ out)
{
    __shared__ double sd[32];
    const int tid = threadIdx.x;
    double s = 0.0;
    for (int i = tid; i < BDIM; i += blockDim.x) s += (double)g_rowloss[i];
    #pragma unroll
    for (int o = 16; o; o >>= 1) s += __shfl_xor_sync(0xffffffffu, s, o);
    if (!(tid & 31)) sd[tid >> 5] = s;
    __syncthreads();
    if (tid < 32){
        double x = (tid < (int)(blockDim.x >> 5)) ? sd[tid] : 0.0;
        #pragma unroll
        for (int o = 16; o; o >>= 1) x += __shfl_xor_sync(0xffffffffu, x, o);
        if (!tid) out[0] = (float)x;
    }
}

extern "C" void kernel_launch(void* const* d_in, const int* in_sizes, int n_in,
                              void* d_out, int out_size)
{
    const float* output = (const float*)d_in[0];
    const int*   target = (const int*)d_in[1];
    const float* scores = (const float*)d_in[2];

    size_t smem = (size_t)VDIM*4 + (size_t)NGRP*256*4 + (size_t)LISTCAP*4;
    cudaFuncSetAttribute(adalab_kernel,
                         cudaFuncAttributeMaxDynamicSharedMemorySize, (int)smem);

    adalab_kernel<<<BDIM, NTH, smem>>>(output, target, scores);
    finalize_kernel<<<1, 1024>>>((float*)d_out);
}

// round 2
// speedup vs baseline: 3.2059x; 3.2059x over previous
#include <cuda_runtime.h>

#define VDIM   50257
#define BDIM   2048
#define KSEL   500
#define NTH    256
#define NW     8           // warps per CTA
#define NGRP   4           // histogram privatization copies
#define LISTCAP 4096
#define MARGIN_C 0.2f
#define IGNORE_IDX 0

__device__ float g_rowloss[BDIM];

static __device__ __forceinline__ unsigned fkey(float f){
    unsigned u = __float_as_uint(f);
    return (u & 0x80000000u) ? ~u : (u | 0x80000000u);
}
static __device__ __forceinline__ float kinv(unsigned u){
    unsigned b = (u & 0x80000000u) ? (u & 0x7FFFFFFFu) : ~u;
    return __uint_as_float(b);
}

// Find bucket b s.t. S(b+1) < kk <= S(b), S(b)=sum_{x>=b} hist[x]; kk -= S(b+1).
static __device__ __forceinline__ void select_bucket(
    const unsigned* hists, int ngrp, unsigned& kk, unsigned& bucket,
    unsigned* wtot, unsigned* selb, unsigned* selk)
{
    const int tid = threadIdx.x;
    const int lane = tid & 31;
    unsigned cnt = 0, s = 0;
    // NTH == 256: every thread owns one bucket
    for (int g = 0; g < ngrp; ++g) cnt += hists[g*256 + tid];
    s = cnt;
    #pragma unroll
    for (int o = 1; o < 32; o <<= 1){
        unsigned t = __shfl_down_sync(0xffffffffu, s, o);
        if (lane + o < 32) s += t;            // suffix sum within warp
    }
    if (lane == 0) wtot[tid >> 5] = s;
    __syncthreads();
    unsigned Sb = s;
    for (int w = (tid >> 5) + 1; w < 8; ++w) Sb += wtot[w];
    unsigned Snext = Sb - cnt;
    if (Sb >= kk && Snext < kk){ *selb = (unsigned)tid; *selk = kk - Snext; }
    __syncthreads();
    bucket = *selb;
    kk = *selk;
    __syncthreads();
}

__global__ void __launch_bounds__(NTH, 6)
adalab_kernel(const float* __restrict__ output,
              const int*   __restrict__ target,
              const float* __restrict__ scores)
{
    __shared__ unsigned hists[NGRP*256];
    __shared__ unsigned lkey[LISTCAP];
    __shared__ int      lidx[LISTCAP];
    __shared__ float    s_redf[NW];
    __shared__ float    s_rA[NW], s_rB[NW], s_rC[NW];
    __shared__ unsigned s_t2a[NW], s_t2b[NW];
    __shared__ unsigned s_wtot[8];
    __shared__ unsigned s_selb, s_selk;
    __shared__ int      s_nlist;
    __shared__ float    s_ot;

    const int tid  = threadIdx.x;
    const int lane = tid & 31;
    const int wid  = tid >> 5;
    const int row  = blockIdx.x;
    const int tgt  = target[row];
    const float* orow = output + (size_t)row * VDIM;
    const float* srow = scores + (size_t)row * VDIM;
    const float NEGINF = __int_as_float(0xff800000);

    // float4 alignment: both rows share the same element offset parity
    const int a    = (int)((4u - ((unsigned)((size_t)row * VDIM) & 3u)) & 3u);
    const int nvec = (VDIM - a) >> 2;
    const int vend = a + nvec * 4;
    const int NIT  = (nvec + NTH - 1) / NTH;

    for (int i = tid; i < NGRP*256; i += NTH) hists[i] = 0;
    if (tid == 0){ s_nlist = 0; s_ot = orow[tgt]; }
    __syncthreads();

    unsigned* myhist = &hists[(wid & (NGRP-1)) * 256];

    // ---------- pass 1 (fused): omax, top-2 keys, 256-bin top-byte histogram ----------
    float omax = NEGINF;
    unsigned t2a = 0, t2b = 0;

    // scalar prologue/epilogue (<=3 elems each): direct atomics
    {
        int j = tid;
        if (j < a){
            float o = orow[j]; omax = fmaxf(omax, o);
            float sv = srow[j];
            unsigned u = (j == tgt || j == IGNORE_IDX) ? 0u : fkey(sv);
            if (u > t2a){ t2b = t2a; t2a = u; } else if (u > t2b) t2b = u;
            atomicAdd(&myhist[u >> 24], 1u);
        }
        j = vend + tid;
        if (j < VDIM){
            float o = orow[j]; omax = fmaxf(omax, o);
            float sv = srow[j];
            unsigned u = (j == tgt || j == IGNORE_IDX) ? 0u : fkey(sv);
            if (u > t2a){ t2b = t2a; t2a = u; } else if (u > t2b) t2b = u;
            atomicAdd(&myhist[u >> 24], 1u);
        }
    }

    for (int it = 0; it < NIT; ++it){
        int q = it*NTH + tid;
        bool in = q < nvec;
        int j = a + q*4;
        float4 o4 = make_float4(NEGINF, NEGINF, NEGINF, NEGINF);
        float4 s4 = make_float4(0.f, 0.f, 0.f, 0.f);
        if (in){
            o4 = *reinterpret_cast<const float4*>(orow + j);
            s4 = *reinterpret_cast<const float4*>(srow + j);
        }
        omax = fmaxf(fmaxf(fmaxf(omax, o4.x), o4.y), fmaxf(o4.z, o4.w));
        const float sv[4] = {s4.x, s4.y, s4.z, s4.w};
        #pragma unroll
        for (int k = 0; k < 4; ++k){
            int jj = j + k;
            unsigned u = (in && jj != tgt && jj != IGNORE_IDX) ? fkey(sv[k]) : 0u;
            if (in){
                if (u > t2a){ t2b = t2a; t2a = u; } else if (u > t2b) t2b = u;
            }
            unsigned d = u >> 24;
            unsigned tag = in ? d : (0x100u + (unsigned)lane);
            unsigned mm = __match_any_sync(0xffffffffu, tag);
            if (in && lane == (__ffs(mm) - 1))
                atomicAdd(&myhist[d], (unsigned)__popc(mm));
        }
    }

    // reduce omax
    #pragma unroll
    for (int o = 16; o; o >>= 1) omax = fmaxf(omax, __shfl_xor_sync(0xffffffffu, omax, o));
    if (!lane) s_redf[wid] = omax;
    // reduce top-2
    #pragma unroll
    for (int o = 16; o; o >>= 1){
        unsigned ya = __shfl_xor_sync(0xffffffffu, t2a, o);
        unsigned yb = __shfl_xor_sync(0xffffffffu, t2b, o);
        if (ya > t2a){ t2b = max(t2a, yb); t2a = ya; }
        else         { t2b = max(t2b, ya); }
    }
    if (!lane){ s_t2a[wid] = t2a; s_t2b[wid] = t2b; }
    __syncthreads();
    if (wid == 0){
        float x = (lane < NW) ? s_redf[lane] : NEGINF;
        unsigned xa = (lane < NW) ? s_t2a[lane] : 0u;
        unsigned xb = (lane < NW) ? s_t2b[lane] : 0u;
        #pragma unroll
        for (int o = 4; o; o >>= 1){
            x = fmaxf(x, __shfl_xor_sync(0xffffffffu, x, o));
            unsigned ya = __shfl_xor_sync(0xffffffffu, xa, o);
            unsigned yb = __shfl_xor_sync(0xffffffffu, xb, o);
            if (ya > xa){ xb = max(xa, yb); xa = ya; }
            else        { xb = max(xb, ya); }
        }
        if (!lane){ s_redf[0] = x; s_t2a[0] = xa; s_t2b[0] = xb; }
    }
    __syncthreads();
    const float    o_max = s_redf[0];
    const float    o_t   = s_ot;
    const unsigned k2key = s_t2b[0];
    const float    s2    = kinv(k2key);

    // ---------- radix round 1 result ----------
    unsigned prefix = 0;
    unsigned kk = KSEL;
    unsigned b1;
    select_bucket(hists, NGRP, kk, b1, s_wtot, &s_selb, &s_selk);
    prefix = b1 << 24;

    // ---------- pass 2: re-read scores (L2-hot), compact candidates top byte >= b1 ----------
    {
        // prologue/epilogue
        #pragma unroll
        for (int seg = 0; seg < 2; ++seg){
            int j = (seg == 0) ? tid : (vend + tid);
            bool valid = (seg == 0) ? (j < a) : (j < VDIM);
            unsigned u = 0u;
            if (valid){
                float sv2 = srow[j];
                u = (j == tgt || j == IGNORE_IDX) ? 0u : fkey(sv2);
            }
            bool ge = valid && ((u >> 24) >= b1);
            unsigned bal = __ballot_sync(0xffffffffu, ge);
            if (bal){
                int ldr = __ffs(bal) - 1;
                int base = 0;
                if (lane == ldr) base = atomicAdd(&s_nlist, __popc(bal));
                base = __shfl_sync(0xffffffffu, base, ldr);
                if (ge){
                    int pos = base + __popc(bal & ((1u << lane) - 1u));
                    if (pos < LISTCAP){ lkey[pos] = u; lidx[pos] = j; }
                }
            }
        }
        for (int it = 0; it < NIT; ++it){
            int q = it*NTH + tid;
            bool in = q < nvec;
            int j = a + q*4;
            float4 s4 = make_float4(0.f, 0.f, 0.f, 0.f);
            if (in) s4 = *reinterpret_cast<const float4*>(srow + j);
            const float sv[4] = {s4.x, s4.y, s4.z, s4.w};
            #pragma unroll
            for (int k = 0; k < 4; ++k){
                int jj = j + k;
                unsigned u = (in && jj != tgt && jj != IGNORE_IDX) ? fkey(sv[k]) : 0u;
                bool ge = in && ((u >> 24) >= b1);
                unsigned bal = __ballot_sync(0xffffffffu, ge);
                if (bal){
                    int ldr = __ffs(bal) - 1;
                    int base = 0;
                    if (lane == ldr) base = atomicAdd(&s_nlist, __popc(bal));
                    base = __shfl_sync(0xffffffffu, base, ldr);
                    if (ge){
                        int pos = base + __popc(bal & ((1u << lane) - 1u));
                        if (pos < LISTCAP){ lkey[pos] = u; lidx[pos] = jj; }
                    }
                }
            }
        }
    }
    __syncthreads();
    const int  nl      = s_nlist;
    const bool useList = (nl <= LISTCAP);
    const int  ncand   = useList ? nl : VDIM;

    // ---------- radix rounds 2-4 on candidate set ----------
    for (int shift = 16; shift >= 0; shift -= 8){
        for (int i = tid; i < 256; i += NTH) hists[i] = 0;
        __syncthreads();
        const unsigned pref_hi = prefix >> (shift + 8);
        const int nit = (ncand + NTH - 1) / NTH;
        for (int it = 0; it < nit; ++it){
            int i = it*NTH + tid;
            bool in = i < ncand;
            unsigned u = 0u;
            if (in){
                if (useList) u = lkey[i];
                else {
                    float f = srow[i];
                    u = (i == tgt || i == IGNORE_IDX) ? 0u : fkey(f);
                }
            }
            bool ok = in && ((u >> (shift + 8)) == pref_hi);
            unsigned d = (u >> shift) & 255u;
            unsigned tag = ok ? d : (0x100u + (unsigned)lane);
            unsigned mm = __match_any_sync(0xffffffffu, tag);
            if (ok && lane == (__ffs(mm) - 1))
                atomicAdd(&hists[d], (unsigned)__popc(mm));
        }
        __syncthreads();
        unsigned b;
        select_bucket(hists, 1, kk, b, s_wtot, &s_selb, &s_selk);
        prefix |= b << shift;
    }
    const unsigned kthkey = prefix;

    // ---------- final: Z, S1, S2 over kept keys in [kth, k2] ----------
    float Z = 0.f, S1 = 0.f, S2 = 0.f;
    {
        const int nit = (ncand + NTH - 1) / NTH;
        for (int it = 0; it < nit; ++it){
            int i = it*NTH + tid;
            if (i < ncand){
                int j; unsigned u;
                if (useList){ u = lkey[i]; j = lidx[i]; }
                else {
                    j = i;
                    float f = srow[i];
                    u = (i == tgt || i == IGNORE_IDX) ? 0u : fkey(f);
                }
                if (u >= kthkey && u <= k2key){
                    float sv = kinv(u);
                    float e = expf(sv - s2);
                    Z  += e;
                    S1 += e * sv;
                    S2 += e * __ldg(orow + j);
                }
            }
        }
    }
    #pragma unroll
    for (int o = 16; o; o >>= 1){
        Z  += __shfl_xor_sync(0xffffffffu, Z,  o);
        S1 += __shfl_xor_sync(0xffffffffu, S1, o);
        S2 += __shfl_xor_sync(0xffffffffu, S2, o);
    }
    if (!lane){ s_rA[wid] = Z; s_rB[wid] = S1; s_rC[wid] = S2; }
    __syncthreads();
    if (wid == 0){
        float av = (lane < NW) ? s_rA[lane] : 0.f;
        float bv = (lane < NW) ? s_rB[lane] : 0.f;
        float cv = (lane < NW) ? s_rC[lane] : 0.f;
        #pragma unroll
        for (int o = 4; o; o >>= 1){
            av += __shfl_xor_sync(0xffffffffu, av, o);
            bv += __shfl_xor_sync(0xffffffffu, bv, o);
            cv += __shfl_xor_sync(0xffffffffu, cv, o);
        }
        if (!lane){
            float loss = 0.f;
            if (tgt != IGNORE_IDX){
                float Zt = av, S1t = bv, S2t = cv;
                float vmax = 1.0f / Zt;            // max kept softmax prob = e^0 / Z
                float pm = expf(o_max);
                float pg = expf(o_t);
                float eps0 = 1.0f - pm;
                float ub   = 1.0f / (1.0f + vmax) - MARGIN_C;
                float eps1 = (eps0 > ub) ? ub : eps0;
                float al = pg / pm; al *= al;
                float eps = al * eps1;
                float conf = 1.0f - eps;
                if (eps  > 0.f) loss += eps  * (logf(eps)  - s2 - logf(Zt) + (S1t - S2t) / Zt);
                if (conf > 0.f) loss += conf * (logf(conf) - o_t);
            }
            g_rowloss[row] = loss;
        }
    }
}

__global__ void finalize_kernel(float* __restrict__ out)
{
    __shared__ double sd[32];
    const int tid = threadIdx.x;
    double s = 0.0;
    for (int i = tid; i < BDIM; i += blockDim.x) s += (double)g_rowloss[i];
    #pragma unroll
    for (int o = 16; o; o >>= 1) s += __shfl_xor_sync(0xffffffffu, s, o);
    if (!(tid & 31)) sd[tid >> 5] = s;
    __syncthreads();
    if (tid < 32){
        double x = (tid < (int)(blockDim.x >> 5)) ? sd[tid] : 0.0;
        #pragma unroll
        for (int o = 16; o; o >>= 1) x += __shfl_xor_sync(0xffffffffu, x, o);
        if (!tid) out[0] = (float)x;
    }
}

extern "C" void kernel_launch(void* const* d_in, const int* in_sizes, int n_in,
                              void* d_out, int out_size)
{
    const float* output = (const float*)d_in[0];
    const int*   target = (const int*)d_in[1];
    const float* scores = (const float*)d_in[2];

    adalab_kernel<<<BDIM, NTH>>>(output, target, scores);
    finalize_kernel<<<1, 1024>>>((float*)d_out);
}

// round 3
// speedup vs baseline: 3.5451x; 1.1058x over previous
#include <cuda_runtime.h>

#define VDIM   50257
#define BDIM   2048
#define KSEL   500
#define NTH    256
#define NW     8
#define LISTCAP 4096
#define MARGIN_C 0.2f
#define IGNORE_IDX 0

__device__ float    g_rowloss[BDIM];
__device__ unsigned g_done;     // zero-init; reset by last CTA each run

static __device__ __forceinline__ unsigned fkey(float f){
    unsigned u = __float_as_uint(f);
    return (u & 0x80000000u) ? ~u : (u | 0x80000000u);
}
static __device__ __forceinline__ float kinv(unsigned u){
    unsigned b = (u & 0x80000000u) ? (u & 0x7FFFFFFFu) : ~u;
    return __uint_as_float(b);
}

// Find bucket b s.t. S(b+1) < kk <= S(b), S(b)=sum_{x>=b} hist[x]; kk -= S(b+1).
static __device__ __forceinline__ void select_bucket(
    const unsigned* hists, unsigned& kk, unsigned& bucket,
    unsigned* wtot, unsigned* selb, unsigned* selk)
{
    const int tid = threadIdx.x;
    const int lane = tid & 31;
    unsigned cnt = hists[tid];          // NTH==256: one bucket per thread
    unsigned s = cnt;
    #pragma unroll
    for (int o = 1; o < 32; o <<= 1){
        unsigned t = __shfl_down_sync(0xffffffffu, s, o);
        if (lane + o < 32) s += t;      // suffix sum within warp
    }
    if (lane == 0) wtot[tid >> 5] = s;
    __syncthreads();
    unsigned Sb = s;
    for (int w = (tid >> 5) + 1; w < 8; ++w) Sb += wtot[w];
    unsigned Snext = Sb - cnt;
    if (Sb >= kk && Snext < kk){ *selb = (unsigned)tid; *selk = kk - Snext; }
    __syncthreads();
    bucket = *selb;
    kk = *selk;
    __syncthreads();
}

__global__ void __launch_bounds__(NTH, 6)
adalab_kernel(const float* __restrict__ output,
              const int*   __restrict__ target,
              const float* __restrict__ scores,
              float* __restrict__ out)
{
    __shared__ unsigned lkey[LISTCAP];
    __shared__ int      lidx[LISTCAP];
    __shared__ unsigned hists[256];
    __shared__ float    s_f0[NW], s_f1[NW], s_f2[NW];
    __shared__ unsigned s_t2a[NW], s_t2b[NW];
    __shared__ unsigned s_wtot[8];
    __shared__ unsigned s_selb, s_selk;
    __shared__ int      s_nlist;
    __shared__ float    s_ot;
    __shared__ int      s_last;

    const int tid  = threadIdx.x;
    const int lane = tid & 31;
    const int wid  = tid >> 5;
    const int row  = blockIdx.x;
    const int tgt  = target[row];
    const float* orow = output + (size_t)row * VDIM;
    const float* srow = scores + (size_t)row * VDIM;
    const float NEGINF = __int_as_float(0xff800000);

    const int a    = (int)((4u - ((unsigned)((size_t)row * VDIM) & 3u)) & 3u);
    const int nvec = (VDIM - a) >> 2;
    const int vend = a + nvec * 4;
    const int NIT  = (nvec + NTH - 1) / NTH;

    if (tid == 0) s_ot = __ldg(orow + tgt);

    // ---------------- pass A: omax(output) + sum/sumsq(scores) ----------------
    float omax = NEGINF, sum = 0.f, sq = 0.f;
    {
        int j = tid;
        if (j < a){
            omax = fmaxf(omax, __ldcs(orow + j));
            float sv = srow[j]; sum += sv; sq = fmaf(sv, sv, sq);
        }
        j = vend + tid;
        if (j < VDIM){
            omax = fmaxf(omax, __ldcs(orow + j));
            float sv = srow[j]; sum += sv; sq = fmaf(sv, sv, sq);
        }
    }
    for (int it = 0; it < NIT; ++it){
        int q = it*NTH + tid;
        if (q < nvec){
            int j = a + q*4;
            float4 o4 = __ldcs(reinterpret_cast<const float4*>(orow + j));
            float4 s4 = *reinterpret_cast<const float4*>(srow + j);
            omax = fmaxf(fmaxf(fmaxf(omax, o4.x), o4.y), fmaxf(o4.z, o4.w));
            sum += (s4.x + s4.y) + (s4.z + s4.w);
            sq = fmaf(s4.x, s4.x, sq); sq = fmaf(s4.y, s4.y, sq);
            sq = fmaf(s4.z, s4.z, sq); sq = fmaf(s4.w, s4.w, sq);
        }
    }
    #pragma unroll
    for (int o = 16; o; o >>= 1){
        omax = fmaxf(omax, __shfl_xor_sync(0xffffffffu, omax, o));
        sum += __shfl_xor_sync(0xffffffffu, sum, o);
        sq  += __shfl_xor_sync(0xffffffffu, sq,  o);
    }
    if (!lane){ s_f0[wid] = omax; s_f1[wid] = sum; s_f2[wid] = sq; }
    __syncthreads();
    if (wid == 0){
        float x = (lane < NW) ? s_f0[lane] : NEGINF;
        float u = (lane < NW) ? s_f1[lane] : 0.f;
        float v = (lane < NW) ? s_f2[lane] : 0.f;
        #pragma unroll
        for (int o = 4; o; o >>= 1){
            x = fmaxf(x, __shfl_xor_sync(0xffffffffu, x, o));
            u += __shfl_xor_sync(0xffffffffu, u, o);
            v += __shfl_xor_sync(0xffffffffu, v, o);
        }
        if (!lane){ s_f0[0] = x; s_f1[0] = u; s_f2[0] = v; }
    }
    __syncthreads();
    const float o_max = s_f0[0];
    const float o_t   = s_ot;
    const float mean  = s_f1[0] * (1.0f / VDIM);
    const float var   = fmaxf(s_f2[0] * (1.0f / VDIM) - mean*mean, 1e-12f);
    const float sd    = sqrtf(var);

    // ---------------- pass B: threshold compaction (binary search in key space) --
    unsigned lo = 0u, hi = 0xffffffffu;
    unsigned tkey = fkey(mean + 1.8f * sd);
    int  nl = 0;
    bool ok = false;
    for (int iter = 0; iter < 10; ++iter){
        __syncthreads();
        if (tid == 0) s_nlist = 0;
        __syncthreads();
        const float T = kinv(tkey);
        {
            int j = tid;
            if (j < a){
                float sv = srow[j];
                if (sv >= T && j != tgt && j != IGNORE_IDX){
                    int pos = atomicAdd(&s_nlist, 1);
                    if (pos < LISTCAP){ lkey[pos] = fkey(sv); lidx[pos] = j; }
                }
            }
            j = vend + tid;
            if (j < VDIM){
                float sv = srow[j];
                if (sv >= T && j != tgt && j != IGNORE_IDX){
                    int pos = atomicAdd(&s_nlist, 1);
                    if (pos < LISTCAP){ lkey[pos] = fkey(sv); lidx[pos] = j; }
                }
            }
        }
        for (int it = 0; it < NIT; ++it){
            int q = it*NTH + tid;
            if (q < nvec){
                int j = a + q*4;
                float4 s4 = *reinterpret_cast<const float4*>(srow + j);
                const float sv[4] = {s4.x, s4.y, s4.z, s4.w};
                #pragma unroll
                for (int k = 0; k < 4; ++k){
                    int jj = j + k;
                    if (sv[k] >= T && jj != tgt && jj != IGNORE_IDX){
                        int pos = atomicAdd(&s_nlist, 1);
                        if (pos < LISTCAP){ lkey[pos] = fkey(sv[k]); lidx[pos] = jj; }
                    }
                }
            }
        }
        __syncthreads();
        nl = s_nlist;
        if (nl >= KSEL && nl <= LISTCAP){ ok = true; break; }
        if (nl > LISTCAP) lo = tkey; else hi = tkey;
        if (hi - lo < 2u) break;
        tkey = lo + ((hi - lo) >> 1);
    }

    const bool useList = ok;
    const int  ncand   = ok ? nl : VDIM;

    // ---------------- top-2 keys over candidate set ----------------
    unsigned t2a = 0, t2b = 0;
    {
        const int nit = (ncand + NTH - 1) / NTH;
        for (int it = 0; it < nit; ++it){
            int i = it*NTH + tid;
            if (i < ncand){
                unsigned u;
                if (useList) u = lkey[i];
                else {
                    float f = srow[i];
                    u = (i == tgt || i == IGNORE_IDX) ? 0u : fkey(f);
                }
                if (u > t2a){ t2b = t2a; t2a = u; } else if (u > t2b) t2b = u;
            }
        }
    }
    #pragma unroll
    for (int o = 16; o; o >>= 1){
        unsigned ya = __shfl_xor_sync(0xffffffffu, t2a, o);
        unsigned yb = __shfl_xor_sync(0xffffffffu, t2b, o);
        if (ya > t2a){ t2b = max(t2a, yb); t2a = ya; }
        else         { t2b = max(t2b, ya); }
    }
    if (!lane){ s_t2a[wid] = t2a; s_t2b[wid] = t2b; }
    __syncthreads();
    if (wid == 0){
        unsigned xa = (lane < NW) ? s_t2a[lane] : 0u;
        unsigned xb = (lane < NW) ? s_t2b[lane] : 0u;
        #pragma unroll
        for (int o = 4; o; o >>= 1){
            unsigned ya = __shfl_xor_sync(0xffffffffu, xa, o);
            unsigned yb = __shfl_xor_sync(0xffffffffu, xb, o);
            if (ya > xa){ xb = max(xa, yb); xa = ya; }
            else        { xb = max(xb, ya); }
        }
        if (!lane){ s_t2b[0] = xb; }
    }
    __syncthreads();
    const unsigned k2key = s_t2b[0];
    const float    s2    = kinv(k2key);

    // ---------------- exact radix select (4 rounds) over candidates ----------------
    unsigned prefix = 0;
    unsigned kk = KSEL;
    for (int shift = 24; shift >= 0; shift -= 8){
        for (int i = tid; i < 256; i += NTH) hists[i] = 0;
        __syncthreads();
        const bool first = (shift == 24);
        const unsigned pref_hi = first ? 0u : (prefix >> (shift + 8));
        const int nit = (ncand + NTH - 1) / NTH;
        for (int it = 0; it < nit; ++it){
            int i = it*NTH + tid;
            bool in = i < ncand;
            unsigned u = 0u;
            if (in){
                if (useList) u = lkey[i];
                else {
                    float f = srow[i];
                    u = (i == tgt || i == IGNORE_IDX) ? 0u : fkey(f);
                }
            }
            bool okd = in && (first || (u >> (shift + 8)) == pref_hi);
            unsigned d = (u >> shift) & 255u;
            unsigned tag = okd ? d : (0x100u + (unsigned)lane);
            unsigned mm = __match_any_sync(0xffffffffu, tag);
            if (okd && lane == (__ffs(mm) - 1))
                atomicAdd(&hists[d], (unsigned)__popc(mm));
        }
        __syncthreads();
        unsigned b;
        select_bucket(hists, kk, b, s_wtot, &s_selb, &s_selk);
        prefix |= b << shift;
    }
    const unsigned kthkey = prefix;

    // ---------------- final: Z, S1, S2 over kept keys in [kth, k2] ----------------
    float Z = 0.f, S1 = 0.f, S2 = 0.f;
    {
        const int nit = (ncand + NTH - 1) / NTH;
        for (int it = 0; it < nit; ++it){
            int i = it*NTH + tid;
            if (i < ncand){
                int j; unsigned u;
                if (useList){ u = lkey[i]; j = lidx[i]; }
                else {
                    j = i;
                    float f = srow[i];
                    u = (i == tgt || i == IGNORE_IDX) ? 0u : fkey(f);
                }
                if (u >= kthkey && u <= k2key){
                    float sv = kinv(u);
                    float e = expf(sv - s2);
                    Z  += e;
                    S1 += e * sv;
                    S2 += e * __ldg(orow + j);
                }
            }
        }
    }
    #pragma unroll
    for (int o = 16; o; o >>= 1){
        Z  += __shfl_xor_sync(0xffffffffu, Z,  o);
        S1 += __shfl_xor_sync(0xffffffffu, S1, o);
        S2 += __shfl_xor_sync(0xffffffffu, S2, o);
    }
    if (!lane){ s_f0[wid] = Z; s_f1[wid] = S1; s_f2[wid] = S2; }
    __syncthreads();
    if (wid == 0){
        float av = (lane < NW) ? s_f0[lane] : 0.f;
        float bv = (lane < NW) ? s_f1[lane] : 0.f;
        float cv = (lane < NW) ? s_f2[lane] : 0.f;
        #pragma unroll
        for (int o = 4; o; o >>= 1){
            av += __shfl_xor_sync(0xffffffffu, av, o);
            bv += __shfl_xor_sync(0xffffffffu, bv, o);
            cv += __shfl_xor_sync(0xffffffffu, cv, o);
        }
        if (!lane){
            float loss = 0.f;
            if (tgt != IGNORE_IDX){
                float Zt = av, S1t = bv, S2t = cv;
                float vmax = 1.0f / Zt;            // max kept softmax prob
                float pm = expf(o_max);
                float pg = expf(o_t);
                float eps0 = 1.0f - pm;
                float ub   = 1.0f / (1.0f + vmax) - MARGIN_C;
                float eps1 = (eps0 > ub) ? ub : eps0;
                float al = pg / pm; al *= al;
                float eps = al * eps1;
                float conf = 1.0f - eps;
                if (eps  > 0.f) loss += eps  * (logf(eps)  - s2 - logf(Zt) + (S1t - S2t) / Zt);
                if (conf > 0.f) loss += conf * (logf(conf) - o_t);
            }
            g_rowloss[row] = loss;
            __threadfence();
            unsigned t = atomicAdd(&g_done, 1u);
            s_last = (t == BDIM - 1u) ? 1 : 0;
        }
    }
    __syncthreads();

    // ---------------- last CTA: deterministic final reduction ----------------
    if (s_last){
        __threadfence();
        __shared__ double sd8[NW];
        double s = 0.0;
        for (int i = tid; i < BDIM; i += NTH) s += (double)g_rowloss[i];
        #pragma unroll
        for (int o = 16; o; o >>= 1) s += __shfl_xor_sync(0xffffffffu, s, o);
        if (!lane) sd8[wid] = s;
        __syncthreads();
        if (tid == 0){
            double x = 0.0;
            #pragma unroll
            for (int w = 0; w < NW; ++w) x += sd8[w];
            out[0] = (float)x;
            g_done = 0;           // reset for next graph replay
        }
    }
}

extern "C" void kernel_launch(void* const* d_in, const int* in_sizes, int n_in,
                              void* d_out, int out_size)
{
    const float* output = (const float*)d_in[0];
    const int*   target = (const int*)d_in[1];
    const float* scores = (const float*)d_in[2];

    adalab_kernel<<<BDIM, NTH>>>(output, target, scores, (float*)d_out);
}

// round 4
// speedup vs baseline: 3.8027x; 1.0727x over previous
#include <cuda_runtime.h>

#define VDIM   50257
#define BDIM   2048
#define KSEL   500
#define NTH    256
#define NW     8
#define LISTCAP 4096
#define SAMPN   2048
#define SCHUNKS 8
#define SRANK   82          // ~2012 expected full-row candidates
#define MARGIN_C 0.2f
#define IGNORE_IDX 0

__device__ float    g_rowloss[BDIM];
__device__ unsigned g_done;

static __device__ __forceinline__ unsigned fkey(float f){
    unsigned u = __float_as_uint(f);
    return (u & 0x80000000u) ? ~u : (u | 0x80000000u);
}
static __device__ __forceinline__ float kinv(unsigned u){
    unsigned b = (u & 0x80000000u) ? (u & 0x7FFFFFFFu) : ~u;
    return __uint_as_float(b);
}

// Find bucket b s.t. S(b+1) < kk <= S(b), S(b)=sum_{x>=b} hist[x]; kk -= S(b+1).
static __device__ __forceinline__ void select_bucket(
    const unsigned* hists, unsigned& kk, unsigned& bucket,
    unsigned* wtot, unsigned* selb, unsigned* selk)
{
    const int tid = threadIdx.x;
    const int lane = tid & 31;
    unsigned cnt = hists[tid];
    unsigned s = cnt;
    #pragma unroll
    for (int o = 1; o < 32; o <<= 1){
        unsigned t = __shfl_down_sync(0xffffffffu, s, o);
        if (lane + o < 32) s += t;
    }
    if (lane == 0) wtot[tid >> 5] = s;
    __syncthreads();
    unsigned Sb = s;
    for (int w = (tid >> 5) + 1; w < 8; ++w) Sb += wtot[w];
    unsigned Snext = Sb - cnt;
    if (Sb >= kk && Snext < kk){ *selb = (unsigned)tid; *selk = kk - Snext; }
    __syncthreads();
    bucket = *selb;
    kk = *selk;
    __syncthreads();
}

// Exact kk-th largest key in smem array keys[0..n). All threads participate.
static __device__ unsigned radix_select(const unsigned* keys, int n, unsigned kk,
                                        unsigned* hists, unsigned* wtot,
                                        unsigned* selb, unsigned* selk)
{
    const int tid = threadIdx.x;
    const int lane = tid & 31;
    unsigned prefix = 0;
    for (int shift = 24; shift >= 0; shift -= 8){
        hists[tid] = 0;
        __syncthreads();
        const bool first = (shift == 24);
        const unsigned pref_hi = first ? 0u : (prefix >> (shift + 8));
        const int nit = (n + NTH - 1) / NTH;
        for (int it = 0; it < nit; ++it){
            int i = it*NTH + tid;
            bool in = i < n;
            unsigned u = in ? keys[i] : 0u;
            bool okd = in && (first || (u >> (shift + 8)) == pref_hi);
            unsigned d = (u >> shift) & 255u;
            unsigned tag = okd ? d : (0x100u + (unsigned)lane);
            unsigned mm = __match_any_sync(0xffffffffu, tag);
            if (okd && lane == (__ffs(mm) - 1))
                atomicAdd(&hists[d], (unsigned)__popc(mm));
        }
        __syncthreads();
        unsigned b;
        select_bucket(hists, kk, b, wtot, selb, selk);
        prefix |= b << shift;
    }
    return prefix;
}

__global__ void __launch_bounds__(NTH, 6)
adalab_kernel(const float* __restrict__ output,
              const int*   __restrict__ target,
              const float* __restrict__ scores,
              float* __restrict__ out)
{
    __shared__ unsigned lkey[LISTCAP];
    __shared__ float    lout[LISTCAP];
    __shared__ unsigned hists[256];
    __shared__ float    s_f0[NW], s_f1[NW], s_f2[NW];
    __shared__ unsigned s_t2a[NW], s_t2b[NW];
    __shared__ unsigned s_wtot[8];
    __shared__ unsigned s_selb, s_selk;
    __shared__ int      s_nlist;
    __shared__ float    s_ot;
    __shared__ int      s_last;

    const int tid  = threadIdx.x;
    const int lane = tid & 31;
    const int wid  = tid >> 5;
    const int row  = blockIdx.x;
    const int tgt  = target[row];
    const float* orow = output + (size_t)row * VDIM;
    const float* srow = scores + (size_t)row * VDIM;
    const float NEGINF = __int_as_float(0xff800000);

    const int a    = (int)((4u - ((unsigned)((size_t)row * VDIM) & 3u)) & 3u);
    const int nvec = (VDIM - a) >> 2;
    const int vend = a + nvec * 4;

    if (tid == 0) s_ot = __ldg(orow + tgt);

    // ---------------- sample pass: 8 spread chunks of 256 scores ----------------
    #pragma unroll
    for (int c = 0; c < SCHUNKS; ++c){
        int base = (c * (VDIM - 256)) / (SCHUNKS - 1);
        lkey[c*NTH + tid] = fkey(srow[base + tid]);
    }
    __syncthreads();
    unsigned tkey = radix_select(lkey, SAMPN, SRANK, hists, s_wtot, &s_selb, &s_selk);

    // ---------------- fused full pass: omax + threshold compaction ----------------
    float omax = NEGINF;
    {
        __syncthreads();
        if (tid == 0) s_nlist = 0;
        __syncthreads();
        const float T = kinv(tkey);
        // scalar prologue / epilogue
        {
            int j = tid;
            if (j < a){
                float o = __ldcs(orow + j); omax = fmaxf(omax, o);
                float sv = srow[j];
                if (sv >= T && j != tgt && j != IGNORE_IDX){
                    int pos = atomicAdd(&s_nlist, 1);
                    if (pos < LISTCAP){ lkey[pos] = fkey(sv); lout[pos] = o; }
                }
            }
            j = vend + tid;
            if (j < VDIM){
                float o = __ldcs(orow + j); omax = fmaxf(omax, o);
                float sv = srow[j];
                if (sv >= T && j != tgt && j != IGNORE_IDX){
                    int pos = atomicAdd(&s_nlist, 1);
                    if (pos < LISTCAP){ lkey[pos] = fkey(sv); lout[pos] = o; }
                }
            }
        }
        // bulk, 2x unrolled: 4 independent 128-bit loads in flight
        int q = tid;
        for (; q + NTH < nvec; q += 2*NTH){
            int j1 = a + q*4, j2 = a + (q + NTH)*4;
            float4 o4a = __ldcs(reinterpret_cast<const float4*>(orow + j1));
            float4 s4a = *reinterpret_cast<const float4*>(srow + j1);
            float4 o4b = __ldcs(reinterpret_cast<const float4*>(orow + j2));
            float4 s4b = *reinterpret_cast<const float4*>(srow + j2);
            omax = fmaxf(fmaxf(fmaxf(omax, o4a.x), o4a.y), fmaxf(o4a.z, o4a.w));
            omax = fmaxf(fmaxf(fmaxf(omax, o4b.x), o4b.y), fmaxf(o4b.z, o4b.w));
            const float sva[4] = {s4a.x, s4a.y, s4a.z, s4a.w};
            const float ova[4] = {o4a.x, o4a.y, o4a.z, o4a.w};
            const float svb[4] = {s4b.x, s4b.y, s4b.z, s4b.w};
            const float ovb[4] = {o4b.x, o4b.y, o4b.z, o4b.w};
            #pragma unroll
            for (int k = 0; k < 4; ++k){
                int jj = j1 + k;
                if (sva[k] >= T && jj != tgt && jj != IGNORE_IDX){
                    int pos = atomicAdd(&s_nlist, 1);
                    if (pos < LISTCAP){ lkey[pos] = fkey(sva[k]); lout[pos] = ova[k]; }
                }
            }
            #pragma unroll
            for (int k = 0; k < 4; ++k){
                int jj = j2 + k;
                if (svb[k] >= T && jj != tgt && jj != IGNORE_IDX){
                    int pos = atomicAdd(&s_nlist, 1);
                    if (pos < LISTCAP){ lkey[pos] = fkey(svb[k]); lout[pos] = ovb[k]; }
                }
            }
        }
        if (q < nvec){
            int j1 = a + q*4;
            float4 o4 = __ldcs(reinterpret_cast<const float4*>(orow + j1));
            float4 s4 = *reinterpret_cast<const float4*>(srow + j1);
            omax = fmaxf(fmaxf(fmaxf(omax, o4.x), o4.y), fmaxf(o4.z, o4.w));
            const float sv[4] = {s4.x, s4.y, s4.z, s4.w};
            const float ov[4] = {o4.x, o4.y, o4.z, o4.w};
            #pragma unroll
            for (int k = 0; k < 4; ++k){
                int jj = j1 + k;
                if (sv[k] >= T && jj != tgt && jj != IGNORE_IDX){
                    int pos = atomicAdd(&s_nlist, 1);
                    if (pos < LISTCAP){ lkey[pos] = fkey(sv[k]); lout[pos] = ov[k]; }
                }
            }
        }
    }
    // reduce omax
    #pragma unroll
    for (int o = 16; o; o >>= 1) omax = fmaxf(omax, __shfl_xor_sync(0xffffffffu, omax, o));
    if (!lane) s_f0[wid] = omax;
    __syncthreads();
    if (wid == 0){
        float x = (lane < NW) ? s_f0[lane] : NEGINF;
        #pragma unroll
        for (int o = 4; o; o >>= 1) x = fmaxf(x, __shfl_xor_sync(0xffffffffu, x, o));
        if (!lane) s_f0[0] = x;
    }
    __syncthreads();
    const float o_max = s_f0[0];
    const float o_t   = s_ot;

    int  nl = s_nlist;
    bool ok = (nl >= KSEL && nl <= LISTCAP);

    // ---------------- rare: binary-search rescan on threshold key ----------------
    if (!ok){
        unsigned lo = 0u, hi = 0xffffffffu;
        if (nl > LISTCAP) lo = tkey; else hi = tkey;
        for (int iter = 0; iter < 12 && hi - lo >= 2u; ++iter){
            tkey = lo + ((hi - lo) >> 1);
            __syncthreads();
            if (tid == 0) s_nlist = 0;
            __syncthreads();
            const float T = kinv(tkey);
            for (int j = tid; j < VDIM; j += NTH){
                float sv = srow[j];
                if (sv >= T && j != tgt && j != IGNORE_IDX){
                    int pos = atomicAdd(&s_nlist, 1);
                    if (pos < LISTCAP){ lkey[pos] = fkey(sv); lout[pos] = __ldg(orow + j); }
                }
            }
            __syncthreads();
            nl = s_nlist;
            if (nl >= KSEL && nl <= LISTCAP){ ok = true; break; }
            if (nl > LISTCAP) lo = tkey; else hi = tkey;
        }
    }

    const bool useList = ok;
    const int  ncand   = ok ? nl : VDIM;

    // ---------------- top-2 keys over candidate set ----------------
    unsigned t2a = 0, t2b = 0;
    {
        const int nit = (ncand + NTH - 1) / NTH;
        for (int it = 0; it < nit; ++it){
            int i = it*NTH + tid;
            if (i < ncand){
                unsigned u;
                if (useList) u = lkey[i];
                else {
                    float f = srow[i];
                    u = (i == tgt || i == IGNORE_IDX) ? 0u : fkey(f);
                }
                if (u > t2a){ t2b = t2a; t2a = u; } else if (u > t2b) t2b = u;
            }
        }
    }
    #pragma unroll
    for (int o = 16; o; o >>= 1){
        unsigned ya = __shfl_xor_sync(0xffffffffu, t2a, o);
        unsigned yb = __shfl_xor_sync(0xffffffffu, t2b, o);
        if (ya > t2a){ t2b = max(t2a, yb); t2a = ya; }
        else         { t2b = max(t2b, ya); }
    }
    if (!lane){ s_t2a[wid] = t2a; s_t2b[wid] = t2b; }
    __syncthreads();
    if (wid == 0){
        unsigned xa = (lane < NW) ? s_t2a[lane] : 0u;
        unsigned xb = (lane < NW) ? s_t2b[lane] : 0u;
        #pragma unroll
        for (int o = 4; o; o >>= 1){
            unsigned ya = __shfl_xor_sync(0xffffffffu, xa, o);
            unsigned yb = __shfl_xor_sync(0xffffffffu, xb, o);
            if (ya > xa){ xb = max(xa, yb); xa = ya; }
            else        { xb = max(xb, ya); }
        }
        if (!lane) s_t2b[0] = xb;
    }
    __syncthreads();
    const unsigned k2key = s_t2b[0];
    const float    s2    = kinv(k2key);

    // ---------------- exact 500th-largest ----------------
    unsigned kthkey;
    if (useList){
        kthkey = radix_select(lkey, ncand, KSEL, hists, s_wtot, &s_selb, &s_selk);
    } else {
        // full-array exact radix (slow fallback, exactness guarantee)
        unsigned prefix = 0, kk = KSEL;
        for (int shift = 24; shift >= 0; shift -= 8){
            hists[tid] = 0;
            __syncthreads();
            const bool first = (shift == 24);
            const unsigned pref_hi = first ? 0u : (prefix >> (shift + 8));
            const int nit = (VDIM + NTH - 1) / NTH;
            for (int it = 0; it < nit; ++it){
                int i = it*NTH + tid;
                bool in = i < VDIM;
                unsigned u = 0u;
                if (in){
                    float f = srow[i];
                    u = (i == tgt || i == IGNORE_IDX) ? 0u : fkey(f);
                }
                bool okd = in && (first || (u >> (shift + 8)) == pref_hi);
                unsigned d = (u >> shift) & 255u;
                unsigned tag = okd ? d : (0x100u + (unsigned)lane);
                unsigned mm = __match_any_sync(0xffffffffu, tag);
                if (okd && lane == (__ffs(mm) - 1))
                    atomicAdd(&hists[d], (unsigned)__popc(mm));
            }
            __syncthreads();
            unsigned b;
            select_bucket(hists, kk, b, s_wtot, &s_selb, &s_selk);
            prefix |= b << shift;
        }
        kthkey = prefix;
    }

    // ---------------- final: Z, S1, S2 over kept keys in [kth, k2] ----------------
    float Z = 0.f, S1 = 0.f, S2 = 0.f;
    {
        const int nit = (ncand + NTH - 1) / NTH;
        for (int it = 0; it < nit; ++it){
            int i = it*NTH + tid;
            if (i < ncand){
                unsigned u; float ov;
                if (useList){ u = lkey[i]; ov = lout[i]; }
                else {
                    float f = srow[i];
                    u = (i == tgt || i == IGNORE_IDX) ? 0u : fkey(f);
                    ov = 0.f;
                }
                if (u >= kthkey && u <= k2key){
                    if (!useList) ov = __ldg(orow + i);
                    float sv = kinv(u);
                    float e = expf(sv - s2);
                    Z  += e;
                    S1 += e * sv;
                    S2 += e * ov;
                }
            }
        }
    }
    #pragma unroll
    for (int o = 16; o; o >>= 1){
        Z  += __shfl_xor_sync(0xffffffffu, Z,  o);
        S1 += __shfl_xor_sync(0xffffffffu, S1, o);
        S2 += __shfl_xor_sync(0xffffffffu, S2, o);
    }
    if (!lane){ s_f0[wid] = Z; s_f1[wid] = S1; s_f2[wid] = S2; }
    __syncthreads();
    if (wid == 0){
        float av = (lane < NW) ? s_f0[lane] : 0.f;
        float bv = (lane < NW) ? s_f1[lane] : 0.f;
        float cv = (lane < NW) ? s_f2[lane] : 0.f;
        #pragma unroll
        for (int o = 4; o; o >>= 1){
            av += __shfl_xor_sync(0xffffffffu, av, o);
            bv += __shfl_xor_sync(0xffffffffu, bv, o);
            cv += __shfl_xor_sync(0xffffffffu, cv, o);
        }
        if (!lane){
            float loss = 0.f;
            if (tgt != IGNORE_IDX){
                float Zt = av, S1t = bv, S2t = cv;
                float vmax = 1.0f / Zt;
                float pm = expf(o_max);
                float pg = expf(o_t);
                float eps0 = 1.0f - pm;
                float ub   = 1.0f / (1.0f + vmax) - MARGIN_C;
                float eps1 = (eps0 > ub) ? ub : eps0;
                float al = pg / pm; al *= al;
                float eps = al * eps1;
                float conf = 1.0f - eps;
                if (eps  > 0.f) loss += eps  * (logf(eps)  - s2 - logf(Zt) + (S1t - S2t) / Zt);
                if (conf > 0.f) loss += conf * (logf(conf) - o_t);
            }
            g_rowloss[row] = loss;
            __threadfence();
            unsigned t = atomicAdd(&g_done, 1u);
            s_last = (t == BDIM - 1u) ? 1 : 0;
        }
    }
    __syncthreads();

    // ---------------- last CTA: deterministic final reduction ----------------
    if (s_last){
        __threadfence();
        __shared__ double sd8[NW];
        double s = 0.0;
        for (int i = tid; i < BDIM; i += NTH) s += (double)g_rowloss[i];
        #pragma unroll
        for (int o = 16; o; o >>= 1) s += __shfl_xor_sync(0xffffffffu, s, o);
        if (!lane) sd8[wid] = s;
        __syncthreads();
        if (tid == 0){
            double x = 0.0;
            #pragma unroll
            for (int w = 0; w < NW; ++w) x += sd8[w];
            out[0] = (float)x;
            g_done = 0;
        }
    }
}

extern "C" void kernel_launch(void* const* d_in, const int* in_sizes, int n_in,
                              void* d_out, int out_size)
{
    const float* output = (const float*)d_in[0];
    const int*   target = (const int*)d_in[1];
    const float* scores = (const float*)d_in[2];

    adalab_kernel<<<BDIM, NTH>>>(output, target, scores, (float*)d_out);
}